// round 12
// baseline (speedup 1.0000x reference)
#include <cuda_runtime.h>
#include <cstdint>
#include <math.h>

#define NMAX  100000
#define EMAX  3200000
#define FIN   128
#define C1    16
#define C2    8

// Scratch (device globals; allocation-free per harness rules)
__device__ __align__(16) int    g_deg [NMAX];
__device__ __align__(16) float2 g_nd1 [NMAX];   // {ys = dinv*y, dinv}
__device__ __align__(16) float2 g_acc [NMAX];   // {Σ ys, Σ dinv_s} (seeded w/ self)
__device__ __align__(16) float  g_dinv[NMAX];
__device__ __align__(16) float  g_p   [NMAX];   // p = dinv*v (agg2 gather src)
__device__ __align__(16) float  g_gg  [NMAX];   // layer-2 accum (seeded w/ p)
__device__ __align__(16) float  g_sf  [NMAX];   // sfull
__device__ __align__(16) float  g_z   [NMAX];
__device__ __align__(16) float  g_m   [FIN];    // W1 @ W2 @ Wl
__device__ float g_alpha, g_beta;

// fp32 reductions, no return
__device__ __forceinline__ void red_add_v2(float2* addr, float a, float b) {
    asm volatile(
        "{\n\t"
        ".reg .u64 ga;\n\t"
        "cvta.to.global.u64 ga, %0;\n\t"
        "red.global.add.v2.f32 [ga], {%1, %2};\n\t"
        "}"
        :: "l"(addr), "f"(a), "f"(b) : "memory");
}
__device__ __forceinline__ void red_add_f(float* addr, float a) {
    asm volatile(
        "{\n\t"
        ".reg .u64 ga;\n\t"
        "cvta.to.global.u64 ga, %0;\n\t"
        "red.global.add.f32 [ga], %1;\n\t"
        "}"
        :: "l"(addr), "f"(a) : "memory");
}

// ---------------------------------------------------------------------------
// K1: degree count (2 edges/thread) + weight fold piggybacked on block 0.
// Fold finishes long before gemm_y launches (kernel ordering in-stream).
__global__ void k_deg(const int* __restrict__ dst,
                      const float* __restrict__ W1, const float* __restrict__ b1,
                      const float* __restrict__ W2, const float* __restrict__ b2,
                      const float* __restrict__ Wl, const float* __restrict__ bl,
                      int E) {
    if (blockIdx.x == 0) {
        int tt = threadIdx.x;
        if (tt < FIN) {
            float acc = 0.0f;
#pragma unroll
            for (int j = 0; j < C1; j++) {
                float inner = 0.0f;
#pragma unroll
                for (int k = 0; k < C2; k++) inner += W2[j * C2 + k] * Wl[k];
                acc += W1[tt * C1 + j] * inner;
            }
            g_m[tt] = acc;
        }
        if (tt == 0) {
            float alpha = 0.0f, beta = bl[0];
#pragma unroll
            for (int k = 0; k < C2; k++) {
                float ck = 0.0f;
#pragma unroll
                for (int j = 0; j < C1; j++) ck += b1[j] * W2[j * C2 + k];
                alpha += ck * Wl[k];
                beta  += b2[k] * Wl[k];
            }
            g_alpha = alpha;
            g_beta  = beta;
        }
    }
    int t = blockIdx.x * blockDim.x + threadIdx.x;
    int e0 = t * 2;
    if (e0 + 1 < E) {
        int2 d2 = reinterpret_cast<const int2*>(dst)[t];
        atomicAdd(&g_deg[d2.x], 1);
        atomicAdd(&g_deg[d2.y], 1);
    } else if (e0 < E) {
        atomicAdd(&g_deg[dst[e0]], 1);
    }
}

// K2: warp-per-node: y = x·m; emit nd1 = {dinv*y, dinv}, seed acc with it.
__global__ __launch_bounds__(256) void k_gemm_y(const float* __restrict__ x, int n) {
    int warp = (blockIdx.x * blockDim.x + threadIdx.x) >> 5;
    int lane = threadIdx.x & 31;
    if (warp >= n) return;
    float4 xv = reinterpret_cast<const float4*>(x)[warp * 32 + lane];
    float4 mv = reinterpret_cast<const float4*>(g_m)[lane];
    float p = xv.x * mv.x + xv.y * mv.y + xv.z * mv.z + xv.w * mv.w;
#pragma unroll
    for (int o = 16; o; o >>= 1) p += __shfl_xor_sync(0xffffffffu, p, o);
    if (lane == 0) {
        float dv = rsqrtf((float)g_deg[warp] + 1.0f);
        float2 nd = make_float2(dv * p, dv);
        g_dinv[warp] = dv;
        g_nd1[warp]  = nd;
        g_acc[warp]  = nd;    // self-loop seed: dinv*y, dinv
    }
}

// K3: agg layer 1 — 2 edges/thread: acc[d] += {ys[s], dinv[s]}
__global__ void k_agg1(const int* __restrict__ src,
                       const int* __restrict__ dst, int E) {
    int t = blockIdx.x * blockDim.x + threadIdx.x;
    int e0 = t * 2;
    if (e0 + 1 < E) {
        int2 s2 = reinterpret_cast<const int2*>(src)[t];
        int2 d2 = reinterpret_cast<const int2*>(dst)[t];
        float2 a = g_nd1[s2.x];
        float2 b = g_nd1[s2.y];
        red_add_v2(&g_acc[d2.x], a.x, a.y);
        red_add_v2(&g_acc[d2.y], b.x, b.y);
    } else if (e0 < E) {
        float2 a = g_nd1[src[e0]];
        red_add_v2(&g_acc[dst[e0]], a.x, a.y);
    }
}

// K4: finalize layer 1 + seed layer 2:
// v = dinv*acc.x ; p = dinv*v ; gg seed = p ; sfull = dinv*acc.y
__global__ void k_mid(int n) {
    int i = blockIdx.x * blockDim.x + threadIdx.x;
    if (i >= n) return;
    float2 a = g_acc[i];
    float dv = g_dinv[i];
    float p  = dv * dv * a.x;
    g_p[i]  = p;
    g_gg[i] = p;                 // self-loop seed for layer 2
    g_sf[i] = dv * a.y;
}

// K5: agg layer 2 — 2 edges/thread: gg[d] += p[s]
__global__ void k_agg2(const int* __restrict__ src,
                       const int* __restrict__ dst, int E) {
    int t = blockIdx.x * blockDim.x + threadIdx.x;
    int e0 = t * 2;
    if (e0 + 1 < E) {
        int2 s2 = reinterpret_cast<const int2*>(src)[t];
        int2 d2 = reinterpret_cast<const int2*>(dst)[t];
        red_add_f(&g_gg[d2.x], g_p[s2.x]);
        red_add_f(&g_gg[d2.y], g_p[s2.y]);
    } else if (e0 < E) {
        red_add_f(&g_gg[dst[e0]], g_p[src[e0]]);
    }
}

// K6: z = sigmoid(dinv*gg + alpha*sfull + beta)
__global__ void k_head(int n) {
    int i = blockIdx.x * blockDim.x + threadIdx.x;
    if (i >= n) return;
    float acc = g_dinv[i] * g_gg[i] + g_alpha * g_sf[i] + g_beta;
    g_z[i] = 1.0f / (1.0f + expf(-acc));
}

// K7: pred[p] = z[pe[p,0]] * z[pe[p,1]]
__global__ void k_pred(const int* __restrict__ pe,
                       float* __restrict__ out, int P) {
    int p = blockIdx.x * blockDim.x + threadIdx.x;
    if (p >= P) return;
    int2 ab = reinterpret_cast<const int2*>(pe)[p];
    out[p] = g_z[ab.x] * g_z[ab.y];
}

extern "C" void kernel_launch(void* const* d_in, const int* in_sizes, int n_in,
                              void* d_out, int out_size) {
    const float* x   = (const float*)d_in[0];
    const int*   ei  = (const int*)d_in[1];
    const int*   pe  = (const int*)d_in[2];
    const float* W1  = (const float*)d_in[3];
    const float* b1  = (const float*)d_in[4];
    const float* W2  = (const float*)d_in[5];
    const float* b2  = (const float*)d_in[6];
    const float* Wl  = (const float*)d_in[7];
    const float* bl  = (const float*)d_in[8];
    float* out = (float*)d_out;

    int n = in_sizes[0] / FIN;
    int E = in_sizes[1] / 2;
    int P = in_sizes[2] / 2;
    if (E > EMAX) E = EMAX;

    const int* src = ei;
    const int* dst = ei + E;

    const int T = 256;

    // zero degree counters via memset node (replaces a kernel launch)
    void* degp = nullptr;
    cudaGetSymbolAddress(&degp, g_deg);
    cudaMemsetAsync(degp, 0, (size_t)n * sizeof(int), 0);

    k_deg   <<<(E / 2 + T - 1) / T, T>>>(dst, W1, b1, W2, b2, Wl, bl, E);
    k_gemm_y<<<(n * 32 + T - 1) / T, T>>>(x, n);
    k_agg1  <<<(E / 2 + T - 1) / T, T>>>(src, dst, E);
    k_mid   <<<(n + T - 1) / T, T>>>(n);
    k_agg2  <<<(E / 2 + T - 1) / T, T>>>(src, dst, E);
    k_head  <<<(n + T - 1) / T, T>>>(n);
    k_pred  <<<(P + T - 1) / T, T>>>(pe, out, P);
}

// round 13
// speedup vs baseline: 1.0634x; 1.0634x over previous
#include <cuda_runtime.h>
#include <cstdint>
#include <math.h>

#define NMAX  100000
#define EMAX  3200000
#define FIN   128
#define C1    16
#define C2    8

// Scratch (device globals; zero-initialized at load; g_deg re-zeroed by k_head
// each call so every invocation starts from a clean counter array)
__device__ __align__(16) int    g_deg [NMAX];
__device__ __align__(16) float2 g_nd1 [NMAX];   // {ys = dinv*y, dinv}
__device__ __align__(16) float2 g_acc [NMAX];   // {Σ ys, Σ dinv_s} (seeded w/ self)
__device__ __align__(16) float  g_dinv[NMAX];
__device__ __align__(16) float  g_p   [NMAX];   // p = dinv*v (agg2 gather src)
__device__ __align__(16) float  g_gg  [NMAX];   // layer-2 accum (seeded w/ p)
__device__ __align__(16) float  g_sf  [NMAX];   // sfull
__device__ __align__(16) float  g_z   [NMAX];
__device__ __align__(16) float  g_m   [FIN];    // W1 @ W2 @ Wl
__device__ float g_alpha, g_beta;

// fp32 reductions, no return
__device__ __forceinline__ void red_add_v2(float2* addr, float a, float b) {
    asm volatile(
        "{\n\t"
        ".reg .u64 ga;\n\t"
        "cvta.to.global.u64 ga, %0;\n\t"
        "red.global.add.v2.f32 [ga], {%1, %2};\n\t"
        "}"
        :: "l"(addr), "f"(a), "f"(b) : "memory");
}
__device__ __forceinline__ void red_add_f(float* addr, float a) {
    asm volatile(
        "{\n\t"
        ".reg .u64 ga;\n\t"
        "cvta.to.global.u64 ga, %0;\n\t"
        "red.global.add.f32 [ga], %1;\n\t"
        "}"
        :: "l"(addr), "f"(a) : "memory");
}

// ---------------------------------------------------------------------------
// K1: degree count (int4, 4 edges/thread) + weight fold on block 0.
__global__ void k_deg(const int* __restrict__ dst,
                      const float* __restrict__ W1, const float* __restrict__ b1,
                      const float* __restrict__ W2, const float* __restrict__ b2,
                      const float* __restrict__ Wl, const float* __restrict__ bl,
                      int E) {
    if (blockIdx.x == 0) {
        int tt = threadIdx.x;
        if (tt < FIN) {
            float acc = 0.0f;
#pragma unroll
            for (int j = 0; j < C1; j++) {
                float inner = 0.0f;
#pragma unroll
                for (int k = 0; k < C2; k++) inner += W2[j * C2 + k] * Wl[k];
                acc += W1[tt * C1 + j] * inner;
            }
            g_m[tt] = acc;
        }
        if (tt == 0) {
            float alpha = 0.0f, beta = bl[0];
#pragma unroll
            for (int k = 0; k < C2; k++) {
                float ck = 0.0f;
#pragma unroll
                for (int j = 0; j < C1; j++) ck += b1[j] * W2[j * C2 + k];
                alpha += ck * Wl[k];
                beta  += b2[k] * Wl[k];
            }
            g_alpha = alpha;
            g_beta  = beta;
        }
    }
    int t = blockIdx.x * blockDim.x + threadIdx.x;
    int e0 = t * 4;
    if (e0 + 3 < E) {
        int4 d4 = reinterpret_cast<const int4*>(dst)[t];
        atomicAdd(&g_deg[d4.x], 1);
        atomicAdd(&g_deg[d4.y], 1);
        atomicAdd(&g_deg[d4.z], 1);
        atomicAdd(&g_deg[d4.w], 1);
    } else {
        for (int e = e0; e < E; e++) atomicAdd(&g_deg[dst[e]], 1);
    }
}

// K2: warp-per-node: y = x·m; emit nd1 = {dinv*y, dinv}, seed acc with it.
__global__ __launch_bounds__(256) void k_gemm_y(const float* __restrict__ x, int n) {
    int warp = (blockIdx.x * blockDim.x + threadIdx.x) >> 5;
    int lane = threadIdx.x & 31;
    if (warp >= n) return;
    float4 xv = reinterpret_cast<const float4*>(x)[warp * 32 + lane];
    float4 mv = reinterpret_cast<const float4*>(g_m)[lane];
    float p = xv.x * mv.x + xv.y * mv.y + xv.z * mv.z + xv.w * mv.w;
#pragma unroll
    for (int o = 16; o; o >>= 1) p += __shfl_xor_sync(0xffffffffu, p, o);
    if (lane == 0) {
        float dv = rsqrtf((float)g_deg[warp] + 1.0f);
        float2 nd = make_float2(dv * p, dv);
        g_dinv[warp] = dv;
        g_nd1[warp]  = nd;
        g_acc[warp]  = nd;    // self-loop seed: dinv*y, dinv
    }
}

// K3: agg layer 1 — 1 edge/thread: acc[d] += {ys[s], dinv[s]}
__global__ void k_agg1(const int* __restrict__ src,
                       const int* __restrict__ dst, int E) {
    int e = blockIdx.x * blockDim.x + threadIdx.x;
    if (e >= E) return;
    float2 nd = g_nd1[src[e]];
    red_add_v2(&g_acc[dst[e]], nd.x, nd.y);
}

// K4: finalize layer 1 + seed layer 2:
// v = dinv*acc.x ; p = dinv*v ; gg seed = p ; sfull = dinv*acc.y
__global__ void k_mid(int n) {
    int i = blockIdx.x * blockDim.x + threadIdx.x;
    if (i >= n) return;
    float2 a = g_acc[i];
    float dv = g_dinv[i];
    float p  = dv * dv * a.x;
    g_p[i]  = p;
    g_gg[i] = p;                 // self-loop seed for layer 2
    g_sf[i] = dv * a.y;
}

// K5: agg layer 2 — 1 edge/thread: gg[d] += p[s]
__global__ void k_agg2(const int* __restrict__ src,
                       const int* __restrict__ dst, int E) {
    int e = blockIdx.x * blockDim.x + threadIdx.x;
    if (e >= E) return;
    red_add_f(&g_gg[dst[e]], g_p[src[e]]);
}

// K6: z = sigmoid(dinv*gg + alpha*sfull + beta); re-zero g_deg for next call
__global__ void k_head(int n) {
    int i = blockIdx.x * blockDim.x + threadIdx.x;
    if (i >= n) return;
    float acc = g_dinv[i] * g_gg[i] + g_alpha * g_sf[i] + g_beta;
    g_z[i] = 1.0f / (1.0f + expf(-acc));
    g_deg[i] = 0;   // restore the "g_deg zeroed" invariant for the next launch
}

// K7: pred[p] = z[pe[p,0]] * z[pe[p,1]]
__global__ void k_pred(const int* __restrict__ pe,
                       float* __restrict__ out, int P) {
    int p = blockIdx.x * blockDim.x + threadIdx.x;
    if (p >= P) return;
    int2 ab = reinterpret_cast<const int2*>(pe)[p];
    out[p] = g_z[ab.x] * g_z[ab.y];
}

extern "C" void kernel_launch(void* const* d_in, const int* in_sizes, int n_in,
                              void* d_out, int out_size) {
    const float* x   = (const float*)d_in[0];
    const int*   ei  = (const int*)d_in[1];
    const int*   pe  = (const int*)d_in[2];
    const float* W1  = (const float*)d_in[3];
    const float* b1  = (const float*)d_in[4];
    const float* W2  = (const float*)d_in[5];
    const float* b2  = (const float*)d_in[6];
    const float* Wl  = (const float*)d_in[7];
    const float* bl  = (const float*)d_in[8];
    float* out = (float*)d_out;

    int n = in_sizes[0] / FIN;
    int E = in_sizes[1] / 2;
    int P = in_sizes[2] / 2;
    if (E > EMAX) E = EMAX;

    const int* src = ei;
    const int* dst = ei + E;

    const int T = 256;

    k_deg   <<<(E / 4 + T - 1) / T, T>>>(dst, W1, b1, W2, b2, Wl, bl, E);
    k_gemm_y<<<(n * 32 + T - 1) / T, T>>>(x, n);
    k_agg1  <<<(E + T - 1) / T, T>>>(src, dst, E);
    k_mid   <<<(n + T - 1) / T, T>>>(n);
    k_agg2  <<<(E + T - 1) / T, T>>>(src, dst, E);
    k_head  <<<(n + T - 1) / T, T>>>(n);
    k_pred  <<<(P + T - 1) / T, T>>>(pe, out, P);
}